// round 8
// baseline (speedup 1.0000x reference)
#include <cuda_runtime.h>
#include <cstdint>

// ---------------------------------------------------------------------------
// Problem constants
// ---------------------------------------------------------------------------
#define M_TOTAL 16384
#define N_W     1024
#define K_TOTAL 1024

// GEMM tiling: CTA 128x128, 8 warps of 64x32, BK=32, 4-stage cp.async ring
#define BM 128
#define BN 128
#define BK 32
#define NITER (K_TOTAL / BK)   // 32
#define STAGES 4

#define RSTRIDE 80                       // bytes per smem row (64 data + 16 pad)
#define STAGE_T (128 * RSTRIDE)          // 10240 B per tile per stage
#define SMEM_BYTES (2 * STAGES * STAGE_T)  // A[4] + B[4] = 81920 B

// Scales: xq = round(x * 2^11), wq = round(w * 2^17); combined 2^28.
#define SX 2048.0f
#define SW 131072.0f
#define INV_SCALE 3.725290298461914e-9f  // 2^-28
#define QCLAMP 16128

// Scratch
__device__ float   g_qkv[3ull * M_TOTAL * N_W];          // QKV projections (fp32)
__device__ int8_t  g_xq[(size_t)M_TOTAL * 2048];         // x rows: per-kc [hi32|lo32]
__device__ int8_t  g_wq[3ull * 8 * 32 * 8192];           // W tiles: [n128][lo32|hi32]

// ---------------------------------------------------------------------------
// Helpers
// ---------------------------------------------------------------------------
__device__ __forceinline__ uint32_t smem_u32(const void* p) {
    uint32_t a;
    asm("{ .reg .u64 t; cvta.to.shared.u64 t, %1; cvt.u32.u64 %0, t; }" : "=r"(a) : "l"(p));
    return a;
}

#define CP_ASYNC_16(dst_u32, src_ptr) \
    asm volatile("cp.async.cg.shared.global [%0], [%1], 16;" \
                 :: "r"(dst_u32), "l"(src_ptr) : "memory")
#define CP_COMMIT() asm volatile("cp.async.commit_group;" ::: "memory")
#define CP_WAIT(n)  asm volatile("cp.async.wait_group %0;" :: "n"(n) : "memory")

#define LDSM_X4(r0, r1, r2, r3, addr) \
    asm volatile("ldmatrix.sync.aligned.m8n8.x4.shared.b16 {%0,%1,%2,%3}, [%4];" \
                 : "=r"(r0), "=r"(r1), "=r"(r2), "=r"(r3) : "r"(addr))

__device__ __forceinline__ void mma_s8(int* d, const uint32_t* a, const uint32_t* b) {
    asm volatile(
        "mma.sync.aligned.m16n8k32.row.col.s32.s8.s8.s32 "
        "{%0,%1,%2,%3}, {%4,%5,%6,%7}, {%8,%9}, {%0,%1,%2,%3};"
        : "+r"(d[0]), "+r"(d[1]), "+r"(d[2]), "+r"(d[3])
        : "r"(a[0]), "r"(a[1]), "r"(a[2]), "r"(a[3]),
          "r"(b[0]), "r"(b[1]));
}

__device__ __forceinline__ uint32_t pack4(int a, int b, int c, int d) {
    return (uint32_t)(a & 0xFF) | ((uint32_t)(b & 0xFF) << 8) |
           ((uint32_t)(c & 0xFF) << 16) | ((uint32_t)(d & 0xFF) << 24);
}

// quantize to 15-bit range and split: q = 128*hi + lo
__device__ __forceinline__ void qsplit(float v, float scale, int& hi, int& lo) {
    int q = __float2int_rn(v * scale);
    q = max(-QCLAMP, min(QCLAMP, q));
    hi = ((q + 16448) >> 7) - 128;       // round-to-nearest
    lo = q - (hi << 7);
}

// ---------------------------------------------------------------------------
// quant_x: x fp32 -> per-row, per-kc chunks of [hi 32B | lo 32B]
// ---------------------------------------------------------------------------
__global__ void __launch_bounds__(256)
quant_x_kernel(const float* __restrict__ x)
{
    const size_t t = (size_t)blockIdx.x * 256 + threadIdx.x;
    const size_t row = t >> 5;
    const int chunk = (int)(t & 31);
    const float* src = x + row * K_TOTAL + chunk * 32;

    int hi[32], lo[32];
    #pragma unroll
    for (int i = 0; i < 8; i++) {
        float4 v = *(const float4*)(src + i * 4);
        qsplit(v.x, SX, hi[i * 4 + 0], lo[i * 4 + 0]);
        qsplit(v.y, SX, hi[i * 4 + 1], lo[i * 4 + 1]);
        qsplit(v.z, SX, hi[i * 4 + 2], lo[i * 4 + 2]);
        qsplit(v.w, SX, hi[i * 4 + 3], lo[i * 4 + 3]);
    }
    uint4 h0, h1, l0, l1;
    h0.x = pack4(hi[0], hi[1], hi[2], hi[3]);    h0.y = pack4(hi[4], hi[5], hi[6], hi[7]);
    h0.z = pack4(hi[8], hi[9], hi[10], hi[11]);  h0.w = pack4(hi[12], hi[13], hi[14], hi[15]);
    h1.x = pack4(hi[16], hi[17], hi[18], hi[19]); h1.y = pack4(hi[20], hi[21], hi[22], hi[23]);
    h1.z = pack4(hi[24], hi[25], hi[26], hi[27]); h1.w = pack4(hi[28], hi[29], hi[30], hi[31]);
    l0.x = pack4(lo[0], lo[1], lo[2], lo[3]);    l0.y = pack4(lo[4], lo[5], lo[6], lo[7]);
    l0.z = pack4(lo[8], lo[9], lo[10], lo[11]);  l0.w = pack4(lo[12], lo[13], lo[14], lo[15]);
    l1.x = pack4(lo[16], lo[17], lo[18], lo[19]); l1.y = pack4(lo[20], lo[21], lo[22], lo[23]);
    l1.z = pack4(lo[24], lo[25], lo[26], lo[27]); l1.w = pack4(lo[28], lo[29], lo[30], lo[31]);

    int8_t* dst = g_xq + row * 2048 + chunk * 64;
    *(uint4*)(dst)      = h0;
    *(uint4*)(dst + 16) = h1;
    *(uint4*)(dst + 32) = l0;
    *(uint4*)(dst + 48) = l1;
}

// ---------------------------------------------------------------------------
// quant_w: W[k][n] -> n-major tiles (w, nb, kc): [n 0..127][lo 32B | hi 32B]
// ---------------------------------------------------------------------------
__global__ void __launch_bounds__(256)
quant_w_kernel(const float* __restrict__ Wq, const float* __restrict__ Wk,
               const float* __restrict__ Wv)
{
    const int kc = blockIdx.x, nb = blockIdx.y, w = blockIdx.z;
    const int n  = threadIdx.x & 127;
    const int kh = threadIdx.x >> 7;
    const float* W = (w == 0) ? Wq : (w == 1 ? Wk : Wv);

    int hi[16], lo[16];
    #pragma unroll
    for (int j = 0; j < 16; j++) {
        float v = W[(size_t)(kc * 32 + kh * 16 + j) * N_W + nb * 128 + n];
        qsplit(v, SW, hi[j], lo[j]);
    }
    uint4 hq, lq;
    lq.x = pack4(lo[0], lo[1], lo[2], lo[3]);    lq.y = pack4(lo[4], lo[5], lo[6], lo[7]);
    lq.z = pack4(lo[8], lo[9], lo[10], lo[11]);  lq.w = pack4(lo[12], lo[13], lo[14], lo[15]);
    hq.x = pack4(hi[0], hi[1], hi[2], hi[3]);    hq.y = pack4(hi[4], hi[5], hi[6], hi[7]);
    hq.z = pack4(hi[8], hi[9], hi[10], hi[11]);  hq.w = pack4(hi[12], hi[13], hi[14], hi[15]);

    int8_t* dst = g_wq + (((size_t)w * 8 + nb) * 32 + kc) * 8192 + (size_t)n * 64;
    *(uint4*)(dst + kh * 16)      = lq;
    *(uint4*)(dst + 32 + kh * 16) = hq;
}

// ---------------------------------------------------------------------------
// Fused QKV GEMM (int8 split, 4-stage pipeline, one barrier per iteration).
// 256 threads, 8 warps (2m x 4n) of 64x32.
// out = (16384*acc_hh + 128*acc_cross) * 2^-28 + bias
// ---------------------------------------------------------------------------
__global__ void __launch_bounds__(256, 1)
qkv_gemm_kernel(const float* __restrict__ bq, const float* __restrict__ bk,
                const float* __restrict__ bv)
{
    extern __shared__ char smem[];
    const uint32_t sA = smem_u32(smem);                 // [STAGES][128][RSTRIDE]
    const uint32_t sB = sA + STAGES * STAGE_T;          // [STAGES][128][RSTRIDE]

    const int tid = threadIdx.x;
    const int wid = tid >> 5;
    const int lane = tid & 31;
    const int r = lane >> 2;
    const int c = lane & 3;

    const int ntile = blockIdx.x;           // 0..23
    const int mtile = blockIdx.y;           // 0..127
    const int wsel  = ntile >> 3;
    const int nb    = ntile & 7;
    const int n0    = nb * BN;
    const int m0    = mtile * BM;
    const int8_t* Wt = g_wq + (((size_t)wsel * 8 + nb) * 32) * 8192;
    const float* bias = (wsel == 0) ? bq : (wsel == 1 ? bk : bv);

    const int wm = wid & 1;                 // 64-row group
    const int wn = wid >> 1;                // 32-col group (0..3)

    const uint32_t laneA = (uint32_t)((lane & 15) * RSTRIDE + (lane >> 4) * 16);
    const uint32_t laneB = (uint32_t)(((lane & 7) + ((lane >> 4) << 3)) * RSTRIDE
                                      + ((lane >> 3) & 1) * 16);

    auto load_tiles = [&](int kc, int buf) {
        const int8_t* Ag = g_xq + (size_t)m0 * 2048 + (size_t)kc * 64;
        const int8_t* Bg = Wt + (size_t)kc * 8192;
        #pragma unroll
        for (int i = 0; i < 2; i++) {
            int idx = tid + i * 256;         // 0..511: A chunks
            int row = idx >> 2, q = idx & 3;
            CP_ASYNC_16(sA + (uint32_t)(buf * STAGE_T + row * RSTRIDE + q * 16),
                        Ag + (size_t)row * 2048 + q * 16);
        }
        #pragma unroll
        for (int i = 0; i < 2; i++) {
            int idx = tid + i * 256;         // 0..511: B chunks
            int row = idx >> 2, q = idx & 3;
            CP_ASYNC_16(sB + (uint32_t)(buf * STAGE_T + row * RSTRIDE + q * 16),
                        Bg + (size_t)row * 64 + q * 16);
        }
        CP_COMMIT();
    };

    int acc_hh[4][4][4], acc_cr[4][4][4];
    #pragma unroll
    for (int mt = 0; mt < 4; mt++)
        #pragma unroll
        for (int nt = 0; nt < 4; nt++)
            #pragma unroll
            for (int i = 0; i < 4; i++) { acc_hh[mt][nt][i] = 0; acc_cr[mt][nt][i] = 0; }

    // Prologue: STAGES-1 tiles in flight.
    load_tiles(0, 0);
    load_tiles(1, 1);
    load_tiles(2, 2);

    for (int kc = 0; kc < NITER; kc++) {
        const int buf = kc & (STAGES - 1);
        CP_WAIT(STAGES - 2);     // load(kc) complete (always 3 groups committed ahead)
        __syncthreads();         // all warps done with buf (kc-1)%STAGES

        // Issue next load into buf (kc-1)%STAGES — safe after the sync above.
        if (kc + STAGES - 1 < NITER)
            load_tiles(kc + STAGES - 1, (kc + STAGES - 1) & (STAGES - 1));
        else
            CP_COMMIT();         // empty group keeps CP_WAIT accounting exact

        const uint32_t aBase = sA + (uint32_t)(buf * STAGE_T + wm * 64 * RSTRIDE) + laneA;
        const uint32_t bBase = sB + (uint32_t)(buf * STAGE_T + wn * 32 * RSTRIDE) + laneB;

        uint32_t aHi[4][4], aLo[4][4];
        #pragma unroll
        for (int mt = 0; mt < 4; mt++) {
            LDSM_X4(aHi[mt][0], aHi[mt][1], aHi[mt][2], aHi[mt][3],
                    aBase + (uint32_t)(mt * 16 * RSTRIDE));
            LDSM_X4(aLo[mt][0], aLo[mt][1], aLo[mt][2], aLo[mt][3],
                    aBase + (uint32_t)(mt * 16 * RSTRIDE) + 32);
        }
        uint32_t bLo[4][2], bHi[4][2];
        #pragma unroll
        for (int pr = 0; pr < 2; pr++) {
            LDSM_X4(bLo[2 * pr][0], bLo[2 * pr][1], bLo[2 * pr + 1][0], bLo[2 * pr + 1][1],
                    bBase + (uint32_t)(pr * 16 * RSTRIDE));
            LDSM_X4(bHi[2 * pr][0], bHi[2 * pr][1], bHi[2 * pr + 1][0], bHi[2 * pr + 1][1],
                    bBase + (uint32_t)(pr * 16 * RSTRIDE) + 32);
        }

        #pragma unroll
        for (int mt = 0; mt < 4; mt++)
            #pragma unroll
            for (int nt = 0; nt < 4; nt++) {
                mma_s8(acc_hh[mt][nt], aHi[mt], bHi[nt]);
                mma_s8(acc_cr[mt][nt], aHi[mt], bLo[nt]);
                mma_s8(acc_cr[mt][nt], aLo[mt], bHi[nt]);
            }
        // No trailing barrier: next iteration's top barrier protects reuse.
    }

    float* dst_w = g_qkv + (size_t)wsel * M_TOTAL * N_W;
    #pragma unroll
    for (int mt = 0; mt < 4; mt++) {
        const int row0 = m0 + wm * 64 + mt * 16 + r;
        #pragma unroll
        for (int nt = 0; nt < 4; nt++) {
            const int col = n0 + wn * 32 + nt * 8 + c * 2;
            const float b0 = __ldg(bias + col);
            const float b1 = __ldg(bias + col + 1);
            float2 v0, v1;
            v0.x = ((float)acc_hh[mt][nt][0] * 16384.f + (float)acc_cr[mt][nt][0] * 128.f) * INV_SCALE + b0;
            v0.y = ((float)acc_hh[mt][nt][1] * 16384.f + (float)acc_cr[mt][nt][1] * 128.f) * INV_SCALE + b1;
            v1.x = ((float)acc_hh[mt][nt][2] * 16384.f + (float)acc_cr[mt][nt][2] * 128.f) * INV_SCALE + b0;
            v1.y = ((float)acc_hh[mt][nt][3] * 16384.f + (float)acc_cr[mt][nt][3] * 128.f) * INV_SCALE + b1;
            *(float2*)(dst_w + (size_t)row0 * N_W + col)       = v0;
            *(float2*)(dst_w + (size_t)(row0 + 8) * N_W + col) = v1;
        }
    }
}

// ---------------------------------------------------------------------------
// Head-attention (best measured config: 75.1 us).
// 4 tokens/block, 128 threads, 32 workers/token.
// ---------------------------------------------------------------------------
#define TPB_T 4
#define RS    68
#define TSTR  (16 * RS + 4)                  // 1092
#define PSTR  16
#define PTOK  (16 * PSTR + 4)                // 260
#define ATTN_SMEM_F (3 * TPB_T * TSTR + TPB_T * PTOK)   // 14144 floats
#define ATTN_SMEM_B (ATTN_SMEM_F * 4)                   // 56576 bytes

__global__ void __launch_bounds__(128, 4)
attn_kernel(float* __restrict__ out)
{
    extern __shared__ float sm[];
    float* sq  = sm;
    float* sk  = sm + TPB_T * TSTR;
    float* sv  = sm + 2 * TPB_T * TSTR;
    float* spT = sm + 3 * TPB_T * TSTR;

    const int tid = threadIdx.x;
    const int t0 = blockIdx.x * TPB_T;

    {
        const float* qg = g_qkv + (size_t)t0 * N_W;
        const float* kg = g_qkv + (size_t)M_TOTAL * N_W + (size_t)t0 * N_W;
        const float* vg = g_qkv + 2ull * M_TOTAL * N_W + (size_t)t0 * N_W;
        #pragma unroll
        for (int i = 0; i < 8; i++) {
            int idx = tid + i * 128;            // 0..1023
            int tok = idx >> 8, rem = idx & 255;
            int row = rem >> 4, dq = rem & 15;
            int sa = tok * TSTR + row * RS + dq * 4;
            size_t ga = (size_t)idx * 4;
            *(float4*)(sq + sa) = *(const float4*)(qg + ga);
            *(float4*)(sk + sa) = *(const float4*)(kg + ga);
            *(float4*)(sv + sa) = *(const float4*)(vg + ga);
        }
    }
    __syncthreads();

    const int tt  = tid >> 5;
    const int sub = tid & 31;
    const int ib  = sub >> 3;
    const int jb  = sub & 7;

    float s[4][2];
    #pragma unroll
    for (int i = 0; i < 4; i++) { s[i][0] = 0.f; s[i][1] = 0.f; }
    {
        const float* qp = sq + tt * TSTR + (ib * 4) * RS;
        const float* kp = sk + tt * TSTR + (jb * 2) * RS;
        #pragma unroll
        for (int dq = 0; dq < 16; dq++) {
            float4 qa[4], ka[2];
            #pragma unroll
            for (int i = 0; i < 4; i++) qa[i] = *(const float4*)(qp + i * RS + dq * 4);
            #pragma unroll
            for (int j = 0; j < 2; j++) ka[j] = *(const float4*)(kp + j * RS + dq * 4);
            #pragma unroll
            for (int i = 0; i < 4; i++)
                #pragma unroll
                for (int j = 0; j < 2; j++) {
                    s[i][j] = fmaf(qa[i].x, ka[j].x, s[i][j]);
                    s[i][j] = fmaf(qa[i].y, ka[j].y, s[i][j]);
                    s[i][j] = fmaf(qa[i].z, ka[j].z, s[i][j]);
                    s[i][j] = fmaf(qa[i].w, ka[j].w, s[i][j]);
                }
        }
    }

    float p[4][2];
    #pragma unroll
    for (int i = 0; i < 4; i++) {
        float s0 = s[i][0] * 0.125f, s1 = s[i][1] * 0.125f;
        float m = fmaxf(s0, s1);
        m = fmaxf(m, __shfl_xor_sync(0xffffffffu, m, 1));
        m = fmaxf(m, __shfl_xor_sync(0xffffffffu, m, 2));
        m = fmaxf(m, __shfl_xor_sync(0xffffffffu, m, 4));
        float e0 = __expf(s0 - m), e1 = __expf(s1 - m);
        float sum = e0 + e1;
        sum += __shfl_xor_sync(0xffffffffu, sum, 1);
        sum += __shfl_xor_sync(0xffffffffu, sum, 2);
        sum += __shfl_xor_sync(0xffffffffu, sum, 4);
        float inv = __frcp_rn(sum);
        p[i][0] = e0 * inv; p[i][1] = e1 * inv;
    }
    {
        float* pt = spT + tt * PTOK;
        #pragma unroll
        for (int j = 0; j < 2; j++) {
            float4 v = make_float4(p[0][j], p[1][j], p[2][j], p[3][j]);
            *(float4*)(pt + (jb * 2 + j) * PSTR + ib * 4) = v;
        }
    }
    __syncwarp();

    {
        const int i0 = (sub >> 4) * 8;
        const int c0 = (sub & 15) * 4;
        const float* pt = spT + tt * PTOK;
        const float* vp = sv + tt * TSTR + c0;
        float4 acc[8];
        #pragma unroll
        for (int i = 0; i < 8; i++) acc[i] = make_float4(0.f, 0.f, 0.f, 0.f);
        #pragma unroll
        for (int j = 0; j < 16; j++) {
            float4 vj = *(const float4*)(vp + j * RS);
            const float* pr = pt + j * PSTR + i0;
            float4 p0 = *(const float4*)(pr);
            float4 p1 = *(const float4*)(pr + 4);
            const float pj[8] = {p0.x, p0.y, p0.z, p0.w, p1.x, p1.y, p1.z, p1.w};
            #pragma unroll
            for (int i = 0; i < 8; i++) {
                acc[i].x = fmaf(pj[i], vj.x, acc[i].x);
                acc[i].y = fmaf(pj[i], vj.y, acc[i].y);
                acc[i].z = fmaf(pj[i], vj.z, acc[i].z);
                acc[i].w = fmaf(pj[i], vj.w, acc[i].w);
            }
        }
        float* ob = out + (size_t)(t0 + tt) * N_W + (size_t)i0 * 64 + c0;
        #pragma unroll
        for (int i = 0; i < 8; i++)
            *(float4*)(ob + i * 64) = acc[i];
    }
}

// ---------------------------------------------------------------------------
// Launch
// ---------------------------------------------------------------------------
extern "C" void kernel_launch(void* const* d_in, const int* in_sizes, int n_in,
                              void* d_out, int out_size)
{
    const float* x  = (const float*)d_in[0];
    const float* Wq = (const float*)d_in[1];
    const float* bq = (const float*)d_in[2];
    const float* Wk = (const float*)d_in[3];
    const float* bk = (const float*)d_in[4];
    const float* Wv = (const float*)d_in[5];
    const float* bv = (const float*)d_in[6];
    float* out = (float*)d_out;

    cudaFuncSetAttribute(qkv_gemm_kernel,
                         cudaFuncAttributeMaxDynamicSharedMemorySize, SMEM_BYTES);
    cudaFuncSetAttribute(attn_kernel,
                         cudaFuncAttributeMaxDynamicSharedMemorySize, ATTN_SMEM_B);

    quant_x_kernel<<<(M_TOTAL * 32) / 256, 256>>>(x);
    {
        dim3 gw(32, 8, 3);
        quant_w_kernel<<<gw, 256>>>(Wq, Wk, Wv);
    }
    dim3 grid(24, 128);
    qkv_gemm_kernel<<<grid, 256, SMEM_BYTES>>>(bq, bk, bv);
    attn_kernel<<<M_TOTAL / TPB_T, 128, ATTN_SMEM_B>>>(out);
}

// round 9
// speedup vs baseline: 1.0790x; 1.0790x over previous
#include <cuda_runtime.h>
#include <cstdint>

// ---------------------------------------------------------------------------
// Problem constants
// ---------------------------------------------------------------------------
#define M_TOTAL 16384
#define N_W     1024
#define K_TOTAL 1024

// GEMM tiling: CTA 128x128, 16 warps of 32x32, BK=32, 4-stage cp.async ring
#define BM 128
#define BN 128
#define BK 32
#define NITER (K_TOTAL / BK)   // 32
#define STAGES 4

#define RSTRIDE 80                       // bytes per smem row (64 data + 16 pad)
#define STAGE_T (128 * RSTRIDE)          // 10240 B per tile per stage
#define SMEM_BYTES (2 * STAGES * STAGE_T)  // A[4] + B[4] = 81920 B

// Scales: xq = round(x * 2^11), wq = round(w * 2^17); combined 2^28.
#define SX 2048.0f
#define SW 131072.0f
#define INV_SCALE 3.725290298461914e-9f  // 2^-28
#define QCLAMP 16128

// Scratch
__device__ float   g_qkv[3ull * M_TOTAL * N_W];          // QKV projections (fp32)
__device__ int8_t  g_xq[(size_t)M_TOTAL * 2048];         // x rows: per-kc [hi32|lo32]
__device__ int8_t  g_wq[3ull * 8 * 32 * 8192];           // W tiles: [n128][lo32|hi32]
__device__ int     g_shift_sink;                         // dummy target

// ---------------------------------------------------------------------------
// Helpers
// ---------------------------------------------------------------------------
__device__ __forceinline__ uint32_t smem_u32(const void* p) {
    uint32_t a;
    asm("{ .reg .u64 t; cvta.to.shared.u64 t, %1; cvt.u32.u64 %0, t; }" : "=r"(a) : "l"(p));
    return a;
}

#define CP_ASYNC_16(dst_u32, src_ptr) \
    asm volatile("cp.async.cg.shared.global [%0], [%1], 16;" \
                 :: "r"(dst_u32), "l"(src_ptr) : "memory")
#define CP_COMMIT() asm volatile("cp.async.commit_group;" ::: "memory")
#define CP_WAIT(n)  asm volatile("cp.async.wait_group %0;" :: "n"(n) : "memory")

#define LDSM_X4(r0, r1, r2, r3, addr) \
    asm volatile("ldmatrix.sync.aligned.m8n8.x4.shared.b16 {%0,%1,%2,%3}, [%4];" \
                 : "=r"(r0), "=r"(r1), "=r"(r2), "=r"(r3) : "r"(addr))

__device__ __forceinline__ void mma_s8(int* d, const uint32_t* a, const uint32_t* b) {
    asm volatile(
        "mma.sync.aligned.m16n8k32.row.col.s32.s8.s8.s32 "
        "{%0,%1,%2,%3}, {%4,%5,%6,%7}, {%8,%9}, {%0,%1,%2,%3};"
        : "+r"(d[0]), "+r"(d[1]), "+r"(d[2]), "+r"(d[3])
        : "r"(a[0]), "r"(a[1]), "r"(a[2]), "r"(a[3]),
          "r"(b[0]), "r"(b[1]));
}

__device__ __forceinline__ uint32_t pack4(int a, int b, int c, int d) {
    return (uint32_t)(a & 0xFF) | ((uint32_t)(b & 0xFF) << 8) |
           ((uint32_t)(c & 0xFF) << 16) | ((uint32_t)(d & 0xFF) << 24);
}

// quantize to 15-bit range and split: q = 128*hi + lo
__device__ __forceinline__ void qsplit(float v, float scale, int& hi, int& lo) {
    int q = __float2int_rn(v * scale);
    q = max(-QCLAMP, min(QCLAMP, q));
    hi = ((q + 16448) >> 7) - 128;       // round-to-nearest
    lo = q - (hi << 7);
}

// ---------------------------------------------------------------------------
// shift_kernel: trivial — exists to shift the GEMM into ncu's captured slot.
// ---------------------------------------------------------------------------
__global__ void shift_kernel()
{
    if (threadIdx.x == 0) g_shift_sink = 1;
}

// ---------------------------------------------------------------------------
// quant_x: x fp32 -> per-row, per-kc chunks of [hi 32B | lo 32B]
// ---------------------------------------------------------------------------
__global__ void __launch_bounds__(256)
quant_x_kernel(const float* __restrict__ x)
{
    const size_t t = (size_t)blockIdx.x * 256 + threadIdx.x;
    const size_t row = t >> 5;
    const int chunk = (int)(t & 31);
    const float* src = x + row * K_TOTAL + chunk * 32;

    int hi[32], lo[32];
    #pragma unroll
    for (int i = 0; i < 8; i++) {
        float4 v = *(const float4*)(src + i * 4);
        qsplit(v.x, SX, hi[i * 4 + 0], lo[i * 4 + 0]);
        qsplit(v.y, SX, hi[i * 4 + 1], lo[i * 4 + 1]);
        qsplit(v.z, SX, hi[i * 4 + 2], lo[i * 4 + 2]);
        qsplit(v.w, SX, hi[i * 4 + 3], lo[i * 4 + 3]);
    }
    uint4 h0, h1, l0, l1;
    h0.x = pack4(hi[0], hi[1], hi[2], hi[3]);    h0.y = pack4(hi[4], hi[5], hi[6], hi[7]);
    h0.z = pack4(hi[8], hi[9], hi[10], hi[11]);  h0.w = pack4(hi[12], hi[13], hi[14], hi[15]);
    h1.x = pack4(hi[16], hi[17], hi[18], hi[19]); h1.y = pack4(hi[20], hi[21], hi[22], hi[23]);
    h1.z = pack4(hi[24], hi[25], hi[26], hi[27]); h1.w = pack4(hi[28], hi[29], hi[30], hi[31]);
    l0.x = pack4(lo[0], lo[1], lo[2], lo[3]);    l0.y = pack4(lo[4], lo[5], lo[6], lo[7]);
    l0.z = pack4(lo[8], lo[9], lo[10], lo[11]);  l0.w = pack4(lo[12], lo[13], lo[14], lo[15]);
    l1.x = pack4(lo[16], lo[17], lo[18], lo[19]); l1.y = pack4(lo[20], lo[21], lo[22], lo[23]);
    l1.z = pack4(lo[24], lo[25], lo[26], lo[27]); l1.w = pack4(lo[28], lo[29], lo[30], lo[31]);

    int8_t* dst = g_xq + row * 2048 + chunk * 64;
    *(uint4*)(dst)      = h0;
    *(uint4*)(dst + 16) = h1;
    *(uint4*)(dst + 32) = l0;
    *(uint4*)(dst + 48) = l1;
}

// ---------------------------------------------------------------------------
// quant_w: W[k][n] -> n-major tiles (w, nb, kc): [n 0..127][lo 32B | hi 32B]
// ---------------------------------------------------------------------------
__global__ void __launch_bounds__(256)
quant_w_kernel(const float* __restrict__ Wq, const float* __restrict__ Wk,
               const float* __restrict__ Wv)
{
    const int kc = blockIdx.x, nb = blockIdx.y, w = blockIdx.z;
    const int n  = threadIdx.x & 127;
    const int kh = threadIdx.x >> 7;
    const float* W = (w == 0) ? Wq : (w == 1 ? Wk : Wv);

    int hi[16], lo[16];
    #pragma unroll
    for (int j = 0; j < 16; j++) {
        float v = W[(size_t)(kc * 32 + kh * 16 + j) * N_W + nb * 128 + n];
        qsplit(v, SW, hi[j], lo[j]);
    }
    uint4 hq, lq;
    lq.x = pack4(lo[0], lo[1], lo[2], lo[3]);    lq.y = pack4(lo[4], lo[5], lo[6], lo[7]);
    lq.z = pack4(lo[8], lo[9], lo[10], lo[11]);  lq.w = pack4(lo[12], lo[13], lo[14], lo[15]);
    hq.x = pack4(hi[0], hi[1], hi[2], hi[3]);    hq.y = pack4(hi[4], hi[5], hi[6], hi[7]);
    hq.z = pack4(hi[8], hi[9], hi[10], hi[11]);  hq.w = pack4(hi[12], hi[13], hi[14], hi[15]);

    int8_t* dst = g_wq + (((size_t)w * 8 + nb) * 32 + kc) * 8192 + (size_t)n * 64;
    *(uint4*)(dst + kh * 16)      = lq;
    *(uint4*)(dst + 32 + kh * 16) = hq;
}

// ---------------------------------------------------------------------------
// Fused QKV GEMM (int8 split, 4-stage pipeline, 512 threads).
// 16 warps (4m x 4n) of 32x32 each -> 4 warps/SMSP at occ 1.
// Per warp-kc: 8 ldsm.x4 + 24 s8 MMAs.
// out = (16384*acc_hh + 128*acc_cross) * 2^-28 + bias
// ---------------------------------------------------------------------------
__global__ void __launch_bounds__(512, 1)
qkv_gemm_kernel(const float* __restrict__ bq, const float* __restrict__ bk,
                const float* __restrict__ bv)
{
    extern __shared__ char smem[];
    const uint32_t sA = smem_u32(smem);                 // [STAGES][128][RSTRIDE]
    const uint32_t sB = sA + STAGES * STAGE_T;          // [STAGES][128][RSTRIDE]

    const int tid = threadIdx.x;
    const int wid = tid >> 5;
    const int lane = tid & 31;
    const int r = lane >> 2;
    const int c = lane & 3;

    const int ntile = blockIdx.x;           // 0..23
    const int mtile = blockIdx.y;           // 0..127
    const int wsel  = ntile >> 3;
    const int nb    = ntile & 7;
    const int n0    = nb * BN;
    const int m0    = mtile * BM;
    const int8_t* Wt = g_wq + (((size_t)wsel * 8 + nb) * 32) * 8192;
    const float* bias = (wsel == 0) ? bq : (wsel == 1 ? bk : bv);

    const int wm = wid & 3;                 // 32-row group (0..3)
    const int wn = wid >> 2;                // 32-col group (0..3)

    const uint32_t laneA = (uint32_t)((lane & 15) * RSTRIDE + (lane >> 4) * 16);
    const uint32_t laneB = (uint32_t)(((lane & 7) + ((lane >> 4) << 3)) * RSTRIDE
                                      + ((lane >> 3) & 1) * 16);

    auto load_tiles = [&](int kc, int buf) {
        const int8_t* Ag = g_xq + (size_t)m0 * 2048 + (size_t)kc * 64;
        const int8_t* Bg = Wt + (size_t)kc * 8192;
        {
            int row = tid >> 2, q = tid & 3;         // 512 chunks each
            CP_ASYNC_16(sA + (uint32_t)(buf * STAGE_T + row * RSTRIDE + q * 16),
                        Ag + (size_t)row * 2048 + q * 16);
            CP_ASYNC_16(sB + (uint32_t)(buf * STAGE_T + row * RSTRIDE + q * 16),
                        Bg + (size_t)row * 64 + q * 16);
        }
        CP_COMMIT();
    };

    int acc_hh[2][4][4], acc_cr[2][4][4];
    #pragma unroll
    for (int mt = 0; mt < 2; mt++)
        #pragma unroll
        for (int nt = 0; nt < 4; nt++)
            #pragma unroll
            for (int i = 0; i < 4; i++) { acc_hh[mt][nt][i] = 0; acc_cr[mt][nt][i] = 0; }

    // Prologue: STAGES-1 tiles in flight.
    load_tiles(0, 0);
    load_tiles(1, 1);
    load_tiles(2, 2);

    for (int kc = 0; kc < NITER; kc++) {
        const int buf = kc & (STAGES - 1);
        CP_WAIT(STAGES - 2);     // load(kc) complete
        __syncthreads();         // all warps done with buf (kc-1)%STAGES

        if (kc + STAGES - 1 < NITER)
            load_tiles(kc + STAGES - 1, (kc + STAGES - 1) & (STAGES - 1));
        else
            CP_COMMIT();         // keep CP_WAIT group accounting exact

        const uint32_t aBase = sA + (uint32_t)(buf * STAGE_T + wm * 32 * RSTRIDE) + laneA;
        const uint32_t bBase = sB + (uint32_t)(buf * STAGE_T + wn * 32 * RSTRIDE) + laneB;

        uint32_t aHi[2][4], aLo[2][4];
        #pragma unroll
        for (int mt = 0; mt < 2; mt++) {
            LDSM_X4(aHi[mt][0], aHi[mt][1], aHi[mt][2], aHi[mt][3],
                    aBase + (uint32_t)(mt * 16 * RSTRIDE));
            LDSM_X4(aLo[mt][0], aLo[mt][1], aLo[mt][2], aLo[mt][3],
                    aBase + (uint32_t)(mt * 16 * RSTRIDE) + 32);
        }
        uint32_t bLo[4][2], bHi[4][2];
        #pragma unroll
        for (int pr = 0; pr < 2; pr++) {
            LDSM_X4(bLo[2 * pr][0], bLo[2 * pr][1], bLo[2 * pr + 1][0], bLo[2 * pr + 1][1],
                    bBase + (uint32_t)(pr * 16 * RSTRIDE));
            LDSM_X4(bHi[2 * pr][0], bHi[2 * pr][1], bHi[2 * pr + 1][0], bHi[2 * pr + 1][1],
                    bBase + (uint32_t)(pr * 16 * RSTRIDE) + 32);
        }

        #pragma unroll
        for (int mt = 0; mt < 2; mt++)
            #pragma unroll
            for (int nt = 0; nt < 4; nt++) {
                mma_s8(acc_hh[mt][nt], aHi[mt], bHi[nt]);
                mma_s8(acc_cr[mt][nt], aHi[mt], bLo[nt]);
                mma_s8(acc_cr[mt][nt], aLo[mt], bHi[nt]);
            }
        // Next iteration's top barrier protects buffer reuse.
    }

    float* dst_w = g_qkv + (size_t)wsel * M_TOTAL * N_W;
    #pragma unroll
    for (int mt = 0; mt < 2; mt++) {
        const int row0 = m0 + wm * 32 + mt * 16 + r;
        #pragma unroll
        for (int nt = 0; nt < 4; nt++) {
            const int col = n0 + wn * 32 + nt * 8 + c * 2;
            const float b0 = __ldg(bias + col);
            const float b1 = __ldg(bias + col + 1);
            float2 v0, v1;
            v0.x = ((float)acc_hh[mt][nt][0] * 16384.f + (float)acc_cr[mt][nt][0] * 128.f) * INV_SCALE + b0;
            v0.y = ((float)acc_hh[mt][nt][1] * 16384.f + (float)acc_cr[mt][nt][1] * 128.f) * INV_SCALE + b1;
            v1.x = ((float)acc_hh[mt][nt][2] * 16384.f + (float)acc_cr[mt][nt][2] * 128.f) * INV_SCALE + b0;
            v1.y = ((float)acc_hh[mt][nt][3] * 16384.f + (float)acc_cr[mt][nt][3] * 128.f) * INV_SCALE + b1;
            *(float2*)(dst_w + (size_t)row0 * N_W + col)       = v0;
            *(float2*)(dst_w + (size_t)(row0 + 8) * N_W + col) = v1;
        }
    }
}

// ---------------------------------------------------------------------------
// Head-attention (best measured config: ~75 us).
// 4 tokens/block, 128 threads, 32 workers/token.
// ---------------------------------------------------------------------------
#define TPB_T 4
#define RS    68
#define TSTR  (16 * RS + 4)                  // 1092
#define PSTR  16
#define PTOK  (16 * PSTR + 4)                // 260
#define ATTN_SMEM_F (3 * TPB_T * TSTR + TPB_T * PTOK)   // 14144 floats
#define ATTN_SMEM_B (ATTN_SMEM_F * 4)                   // 56576 bytes

__global__ void __launch_bounds__(128, 4)
attn_kernel(float* __restrict__ out)
{
    extern __shared__ float sm[];
    float* sq  = sm;
    float* sk  = sm + TPB_T * TSTR;
    float* sv  = sm + 2 * TPB_T * TSTR;
    float* spT = sm + 3 * TPB_T * TSTR;

    const int tid = threadIdx.x;
    const int t0 = blockIdx.x * TPB_T;

    {
        const float* qg = g_qkv + (size_t)t0 * N_W;
        const float* kg = g_qkv + (size_t)M_TOTAL * N_W + (size_t)t0 * N_W;
        const float* vg = g_qkv + 2ull * M_TOTAL * N_W + (size_t)t0 * N_W;
        #pragma unroll
        for (int i = 0; i < 8; i++) {
            int idx = tid + i * 128;            // 0..1023
            int tok = idx >> 8, rem = idx & 255;
            int row = rem >> 4, dq = rem & 15;
            int sa = tok * TSTR + row * RS + dq * 4;
            size_t ga = (size_t)idx * 4;
            *(float4*)(sq + sa) = *(const float4*)(qg + ga);
            *(float4*)(sk + sa) = *(const float4*)(kg + ga);
            *(float4*)(sv + sa) = *(const float4*)(vg + ga);
        }
    }
    __syncthreads();

    const int tt  = tid >> 5;
    const int sub = tid & 31;
    const int ib  = sub >> 3;
    const int jb  = sub & 7;

    float s[4][2];
    #pragma unroll
    for (int i = 0; i < 4; i++) { s[i][0] = 0.f; s[i][1] = 0.f; }
    {
        const float* qp = sq + tt * TSTR + (ib * 4) * RS;
        const float* kp = sk + tt * TSTR + (jb * 2) * RS;
        #pragma unroll
        for (int dq = 0; dq < 16; dq++) {
            float4 qa[4], ka[2];
            #pragma unroll
            for (int i = 0; i < 4; i++) qa[i] = *(const float4*)(qp + i * RS + dq * 4);
            #pragma unroll
            for (int j = 0; j < 2; j++) ka[j] = *(const float4*)(kp + j * RS + dq * 4);
            #pragma unroll
            for (int i = 0; i < 4; i++)
                #pragma unroll
                for (int j = 0; j < 2; j++) {
                    s[i][j] = fmaf(qa[i].x, ka[j].x, s[i][j]);
                    s[i][j] = fmaf(qa[i].y, ka[j].y, s[i][j]);
                    s[i][j] = fmaf(qa[i].z, ka[j].z, s[i][j]);
                    s[i][j] = fmaf(qa[i].w, ka[j].w, s[i][j]);
                }
        }
    }

    float p[4][2];
    #pragma unroll
    for (int i = 0; i < 4; i++) {
        float s0 = s[i][0] * 0.125f, s1 = s[i][1] * 0.125f;
        float m = fmaxf(s0, s1);
        m = fmaxf(m, __shfl_xor_sync(0xffffffffu, m, 1));
        m = fmaxf(m, __shfl_xor_sync(0xffffffffu, m, 2));
        m = fmaxf(m, __shfl_xor_sync(0xffffffffu, m, 4));
        float e0 = __expf(s0 - m), e1 = __expf(s1 - m);
        float sum = e0 + e1;
        sum += __shfl_xor_sync(0xffffffffu, sum, 1);
        sum += __shfl_xor_sync(0xffffffffu, sum, 2);
        sum += __shfl_xor_sync(0xffffffffu, sum, 4);
        float inv = __frcp_rn(sum);
        p[i][0] = e0 * inv; p[i][1] = e1 * inv;
    }
    {
        float* pt = spT + tt * PTOK;
        #pragma unroll
        for (int j = 0; j < 2; j++) {
            float4 v = make_float4(p[0][j], p[1][j], p[2][j], p[3][j]);
            *(float4*)(pt + (jb * 2 + j) * PSTR + ib * 4) = v;
        }
    }
    __syncwarp();

    {
        const int i0 = (sub >> 4) * 8;
        const int c0 = (sub & 15) * 4;
        const float* pt = spT + tt * PTOK;
        const float* vp = sv + tt * TSTR + c0;
        float4 acc[8];
        #pragma unroll
        for (int i = 0; i < 8; i++) acc[i] = make_float4(0.f, 0.f, 0.f, 0.f);
        #pragma unroll
        for (int j = 0; j < 16; j++) {
            float4 vj = *(const float4*)(vp + j * RS);
            const float* pr = pt + j * PSTR + i0;
            float4 p0 = *(const float4*)(pr);
            float4 p1 = *(const float4*)(pr + 4);
            const float pj[8] = {p0.x, p0.y, p0.z, p0.w, p1.x, p1.y, p1.z, p1.w};
            #pragma unroll
            for (int i = 0; i < 8; i++) {
                acc[i].x = fmaf(pj[i], vj.x, acc[i].x);
                acc[i].y = fmaf(pj[i], vj.y, acc[i].y);
                acc[i].z = fmaf(pj[i], vj.z, acc[i].z);
                acc[i].w = fmaf(pj[i], vj.w, acc[i].w);
            }
        }
        float* ob = out + (size_t)(t0 + tt) * N_W + (size_t)i0 * 64 + c0;
        #pragma unroll
        for (int i = 0; i < 8; i++)
            *(float4*)(ob + i * 64) = acc[i];
    }
}

// ---------------------------------------------------------------------------
// Launch
// ---------------------------------------------------------------------------
extern "C" void kernel_launch(void* const* d_in, const int* in_sizes, int n_in,
                              void* d_out, int out_size)
{
    const float* x  = (const float*)d_in[0];
    const float* Wq = (const float*)d_in[1];
    const float* bq = (const float*)d_in[2];
    const float* Wk = (const float*)d_in[3];
    const float* bk = (const float*)d_in[4];
    const float* Wv = (const float*)d_in[5];
    const float* bv = (const float*)d_in[6];
    float* out = (float*)d_out;

    cudaFuncSetAttribute(qkv_gemm_kernel,
                         cudaFuncAttributeMaxDynamicSharedMemorySize, SMEM_BYTES);
    cudaFuncSetAttribute(attn_kernel,
                         cudaFuncAttributeMaxDynamicSharedMemorySize, ATTN_SMEM_B);

    shift_kernel<<<1, 32>>>();   // shifts qkv_gemm into ncu's captured slot
    quant_x_kernel<<<(M_TOTAL * 32) / 256, 256>>>(x);
    {
        dim3 gw(32, 8, 3);
        quant_w_kernel<<<gw, 256>>>(Wq, Wk, Wv);
    }
    dim3 grid(24, 128);
    qkv_gemm_kernel<<<grid, 512, SMEM_BYTES>>>(bq, bk, bv);
    attn_kernel<<<M_TOTAL / TPB_T, 128, ATTN_SMEM_B>>>(out);
}